// round 16
// baseline (speedup 1.0000x reference)
#include <cuda_runtime.h>
#include <cstdint>

// Gather-and-concat (FINAL — converged; byte-identical to the R8 4.544us best):
//   out[b, 0:512]    = lstm1[b, input_length[b]-1, :]
//   out[b, 512:1024] = lstm2[b, support_length[b]-1, :]
// B=64, T=2048, H=512, fp32. Lengths arrive as int32 (JAX silently downcasts
// the reference's int64 without x64 mode).
//
// Convergence evidence (R4-R15):
//   - traffic 512 KB total = <1% HBM; DRAM/L2/L1 <1% busy, issue <5% in every run
//   - body = minimal dependent chain LDG(len) -> IMAD -> LDG.128 -> STG.128;
//     two serial memory accesses is the theoretical minimum for a
//     data-dependent gather (address depends on the length read)
//   - probes: grid 128x128=6.9us, 64x256=4.54us (best), 32x512=4.61us;
//     clamp/no-clamp and 32/64-bit indexing indistinguishable
//   - THIS EXACT SOURCE measured 4.544 / 6.88 / 6.91 / 4.64 / 4.58 us over
//     five runs: timing is bimodal with container clock state, not code.
//     Fast-regime band across three different bodies: 4.54-4.64 us (+-1%) —
//     the signature of a fixed launch/teardown floor.
//   - any remaining edit's predicted effect (<0.1us) is ~20x below the
//     regime noise (2.3us); structural churn from here measures DVFS only.
//
// Shape: 64 CTAs (one per batch) x 256 threads; threads 0-127 copy the lstm1
// half, 128-255 the lstm2 half; one float4 per thread; single wave; 32-bit
// indexing (max offset 16.7M float4s < 2^31). Clamp kept: measured free, and
// converts any dtype surprise into rel_err instead of an illegal access.

static constexpr int B = 64;
static constexpr int T = 2048;
static constexpr int H = 512;

__global__ __launch_bounds__(256, 1)
void vlos_gather_kernel(const float4* __restrict__ lstm1,
                        const float4* __restrict__ lstm2,
                        const int* __restrict__ input_length,
                        const int* __restrict__ support_length,
                        float4* __restrict__ out)
{
    const int b   = blockIdx.x;          // batch 0..63
    const int t   = threadIdx.x;         // 0..255
    const int src = t >> 7;              // 0 = lstm1 half, 1 = lstm2 half
    const int col = t & 127;             // float4 column within the 512-float row

    // Uniform per-half length load (warp-broadcast, single transaction).
    int row = __ldg(src ? &support_length[b] : &input_length[b]) - 1;
    row = max(0, min(T - 1, row));       // defensive: dtype surprises -> rel_err, not crash

    const float4* base = src ? lstm2 : lstm1;
    // 32-bit offsets: (b*T + row) * 128 <= 16.7M, well inside int range.
    const int src_off = (b * T + row) * (H / 4) + col;
    const int dst_off = b * (2 * H / 4) + src * (H / 4) + col;

    out[dst_off] = __ldg(&base[src_off]);
}

extern "C" void kernel_launch(void* const* d_in, const int* in_sizes, int n_in,
                              void* d_out, int out_size)
{
    const float4* lstm1 = (const float4*)d_in[0];
    const float4* lstm2 = (const float4*)d_in[1];
    const int*    ilen  = (const int*)d_in[2];
    const int*    slen  = (const int*)d_in[3];
    float4*       out   = (float4*)d_out;

    vlos_gather_kernel<<<B, 256>>>(lstm1, lstm2, ilen, slen, out);
}